// round 14
// baseline (speedup 1.0000x reference)
#include <cuda_runtime.h>
#include <math.h>
#include <stddef.h>

// Problem constants
#define Bz    32
#define T     1024
#define F     256
#define Hh    256
#define C3    768      // 3 live gate chunks (i, f, g)
#define NB    128      // persistent blocks
#define HB    2        // H columns per block
#define NCOL  6        // HB * 3 chunks
#define NTH   256
#define OMEGA 32

// packed f32x2 helpers (Blackwell)
#define FFMA2(d, a, b) asm("fma.rn.f32x2 %0, %1, %2, %0;" : "+l"(d) : "l"(a), "l"(b))
#define UPK(v, lo, hi) asm("mov.b64 {%0, %1}, %2;" : "=f"(lo), "=f"(hi) : "l"(v))

// -------- device scratch (static; no cudaMalloc) --------
__device__ float g_G[(size_t)T * C3 * Bz];   // [t][col][b]: x@W' cache -> overwritten with Bm[t]=P2@a_cur_t (block-private cols)
__device__ float g_xrs[T];                   // sum_b P_r[b] * (x_t @ W_r)[b]
__device__ float g_pubh[2][Bz * Hh];         // published h, [slot][b*256+k]
__device__ uint2 g_syncp[2][NB];             // packed: {flag, gate-partial} per block, contiguous 1KB/slot
__device__ float g_hfin[Bz * Hh];            // final h for output

// ------------------------------------------------------------------
__global__ void init_kernel() {
    int tid = threadIdx.x;
    for (int i = tid; i < 2 * Bz * Hh; i += NTH) ((float*)g_pubh)[i] = 0.f;
    if (tid < 2 * NB) ((uint2*)g_syncp)[tid] = make_uint2(0u, 0u);
}

// g_xrs[t] = sum_b P_r[b] * sum_f x[b,t,f] * W_r[f]
__global__ __launch_bounds__(256) void xr_kernel(const float* __restrict__ x,
                                                 const float* __restrict__ W_r,
                                                 const float* __restrict__ P_r) {
    __shared__ float xs[32];
    int t = blockIdx.x;
    int tid = threadIdx.x;
    int b = tid >> 3, ks = tid & 7;
    const float4* xv = (const float4*)(x + ((size_t)b * T + t) * F);
    const float4* wr = (const float4*)W_r;
    float s = 0.f;
#pragma unroll
    for (int q = 0; q < 8; q++) {
        float4 a = xv[ks * 8 + q];
        float4 w = wr[ks * 8 + q];
        s += a.x * w.x + a.y * w.y + a.z * w.z + a.w * w.w;
    }
    s += __shfl_xor_sync(0xffffffffu, s, 1);
    s += __shfl_xor_sync(0xffffffffu, s, 2);
    s += __shfl_xor_sync(0xffffffffu, s, 4);
    if (ks == 0) xs[b] = s * P_r[b];
    __syncthreads();
    if (tid < 32) {
        float v = xs[tid];
#pragma unroll
        for (int o = 16; o; o >>= 1) v += __shfl_xor_sync(0xffffffffu, v, o);
        if (tid == 0) g_xrs[t] = v;
    }
}

// G[t][col][b] = sum_f x[b,t,f] * W[f,col], col < 768. Grid: (12 col-tiles, 1024 t).
__global__ __launch_bounds__(256) void gemm_kernel(const float* __restrict__ x,
                                                   const float* __restrict__ W) {
    __shared__ float xsh[Bz][33];
    __shared__ float wsh[32][64];
    int t = blockIdx.y;
    int colbase = blockIdx.x * 64;
    int tid = threadIdx.x;
    int b = tid & 31, cg = tid >> 5;
    unsigned long long acc[4] = {0ull, 0ull, 0ull, 0ull};

    for (int kt = 0; kt < 8; kt++) {
        int k0 = kt * 32;
        __syncthreads();
        {
            int lb = tid >> 3, kq = tid & 7;
            float4 v = *(const float4*)(x + ((size_t)lb * T + t) * F + k0 + kq * 4);
            xsh[lb][kq * 4 + 0] = v.x; xsh[lb][kq * 4 + 1] = v.y;
            xsh[lb][kq * 4 + 2] = v.z; xsh[lb][kq * 4 + 3] = v.w;
            int kk = tid >> 3, c4 = (tid & 7) * 8;
            const float* wrow = W + (size_t)(k0 + kk) * 1024 + colbase + c4;
            *(float4*)&wsh[kk][c4] = *(const float4*)(wrow);
            *(float4*)&wsh[kk][c4 + 4] = *(const float4*)(wrow + 4);
        }
        __syncthreads();
#pragma unroll
        for (int kk = 0; kk < 32; kk++) {
            unsigned xu = __float_as_uint(xsh[b][kk]);
            unsigned long long xx;
            asm("mov.b64 %0, {%1, %1};" : "=l"(xx) : "r"(xu));
            const longlong2* wp = (const longlong2*)&wsh[kk][cg * 8];
            longlong2 w0 = wp[0], w1 = wp[1];
            FFMA2(acc[0], xx, w0.x); FFMA2(acc[1], xx, w0.y);
            FFMA2(acc[2], xx, w1.x); FFMA2(acc[3], xx, w1.y);
        }
    }
    size_t base = (size_t)t * (C3 * Bz) + (size_t)(colbase + cg * 8) * Bz + b;
#pragma unroll
    for (int i = 0; i < 4; i++) {
        float lo, hi; UPK(acc[i], lo, hi);
        g_G[base + (size_t)(2 * i) * Bz] = lo;
        g_G[base + (size_t)(2 * i + 1) * Bz] = hi;
    }
}

// ------------------------------------------------------------------
struct __align__(16) RecSmem {
    float Ush[NCOL][260];          // 6 U' columns, k-contiguous (static)
    float Psh[Bz][68];             // P [32][64] padded (static)
    float pp[2][8][NCOL][Bz];      // per-warp k-split partials, double-buffered by step parity
    float gsh[2][NCOL][Bz];        // G[t] slice (x@W'), double-buffered
    float ac[NCOL][Bz];            // a_cur slice
    float gt[NCOL][Bz];            // gates slice
    unsigned long long psh2[2][8]; // per-warp {tag, payload-sum}, double-buffered
    float Prsh[Bz];
    float biassh[NCOL];
    float s_gpp[2];
    int   sidxsh;
};

__global__ __launch_bounds__(NTH, 1) void rec_kernel(
    const float* __restrict__ U, const float* __restrict__ P,
    const float* __restrict__ B_bias, const float* __restrict__ P_r,
    const float* __restrict__ U_r, const float* __restrict__ W_out,
    const float* __restrict__ b_out, float* __restrict__ out)
{
    extern __shared__ char smem_raw[];
    RecSmem& S = *reinterpret_cast<RecSmem*>(smem_raw);
    const int tid = threadIdx.x;
    const int w = tid >> 5, lane = tid & 31;
    const int bid = blockIdx.x;
    const int j0 = bid * HB;

    // ---- one-time preloads ----
    for (int i = tid; i < NCOL * Hh; i += NTH) {
        int cl = i >> 8, k = i & 255;
        int colg = (cl >> 1) * Hh + j0 + (cl & 1);
        S.Ush[cl][k] = U[(size_t)k * 1024 + colg];
    }
    for (int i = tid; i < Bz * 64; i += NTH) S.Psh[i >> 6][i & 63] = P[i];
    if (tid < Bz) S.Prsh[tid] = P_r[tid];
    if (tid < NCOL) {
        int colg = (tid >> 1) * Hh + j0 + (tid & 1);
        S.biassh[tid] = B_bias[colg];
    }
    if (tid < 48) {   // gsh[0] preload for t=0
        int cl = tid >> 3, qq = tid & 7;
        int colg = (cl >> 1) * Hh + j0 + (cl & 1);
        *(float4*)&S.gsh[0][cl][qq * 4] =
            *(const float4*)&g_G[(size_t)colg * Bz + qq * 4];
    }
    const int mycl = w;                                    // valid for tid<192 stages
    const int mycolg = (mycl >> 1) * Hh + j0 + (mycl & 1);
    float urj = (tid < 64) ? U_r[j0 + w] : 0.f;            // w = jl for tid<64
    float c_reg = 0.f;                                     // c state for (jl=w, b=lane), tid<64
    // matvec lane decomposition: lane = rp*2 + hs; rows rA=rp, rB=rp+16
    const int hs = lane & 1;
    const int rA = lane >> 1;
    const int hbase = rA * 64 + 8 * w + hs;   // longlong2 index into g_pubh row space
    const int ubase = 32 * w + 4 * hs;        // float offset in Ush (+8i per iter)
    __syncthreads();

    for (int t = 0; t < T; t++) {
        const int slot = (t - 1) & 1;   // h published at step t-1 (t=0: both zeroed)
        const int par  = t & 1;
        const bool rec = (t >= OMEGA);

        // ---- P: per-warp poll of OUR 16 producer flags; payload partial sum ----
        float mypay = 0.f;
        if (t > 0) {
            if (lane < 16) {
                const uint2* ap = &g_syncp[slot][16 * w + lane];
                unsigned fl, pv;
                do {
                    asm volatile("ld.acquire.gpu.global.v2.u32 {%0,%1}, [%2];"
                                 : "=r"(fl), "=r"(pv) : "l"(ap) : "memory");
                } while (fl < (unsigned)t);
                mypay = __uint_as_float(pv);
            }
            __syncwarp();
        }
        {
            float v = mypay;
#pragma unroll
            for (int o = 16; o; o >>= 1) v += __shfl_xor_sync(0xffffffffu, v, o);
            if (lane == 0) {
                volatile unsigned long long* ps = &S.psh2[par][w];
                *ps = ((unsigned long long)(unsigned)(t + 1) << 32)
                      | (unsigned long long)__float_as_uint(v);
            }
            // warp0: aggregate 8 warp-sums -> gate -> sidx (only needed when rec)
            if (w == 0 && rec) {
                float pay = 0.f;
                if (lane >= 1 && lane < 8) {
                    volatile unsigned long long* sp = &S.psh2[par][lane];
                    unsigned long long pv;
                    do { pv = *sp; } while ((unsigned)(pv >> 32) != (unsigned)(t + 1));
                    pay = __uint_as_float((unsigned)pv);
                } else if (lane == 0) {
                    pay = v;   // warp0's own full sum
                }
                float g = pay;
                g += __shfl_xor_sync(0xffffffffu, g, 1);
                g += __shfl_xor_sync(0xffffffffu, g, 2);
                g += __shfl_xor_sync(0xffffffffu, g, 4);
                if (lane == 0) {
                    g += g_xrs[t];
                    float gate = 1.f / (1.f + expf(-g));
                    int hi = t - 1;
                    int idx = (int)rintf((float)t * gate);
                    idx = idx < 0 ? 0 : (idx > hi ? hi : idx);
                    S.sidxsh = idx;
                }
            }
        }

        // ---- C: h-slice direct to registers (sector-perfect) + matvec + pair-reduce ----
        {
            const longlong2* hb = (const longlong2*)g_pubh[slot];
            longlong2 hqA[4], hqB[4];
#pragma unroll
            for (int i = 0; i < 4; i++) hqA[i] = __ldcg(&hb[hbase + 2 * i]);
#pragma unroll
            for (int i = 0; i < 4; i++) hqB[i] = __ldcg(&hb[hbase + 1024 + 2 * i]);
            unsigned long long acc[12];
#pragma unroll
            for (int j = 0; j < 12; j++) acc[j] = 0ull;
#pragma unroll
            for (int i = 0; i < 4; i++) {
#pragma unroll
                for (int cl = 0; cl < NCOL; cl++) {
                    longlong2 uv = *(const longlong2*)&S.Ush[cl][ubase + 8 * i];
                    FFMA2(acc[cl * 2 + 0], hqA[i].x, uv.x);
                    FFMA2(acc[cl * 2 + 0], hqA[i].y, uv.y);
                    FFMA2(acc[cl * 2 + 1], hqB[i].x, uv.x);
                    FFMA2(acc[cl * 2 + 1], hqB[i].y, uv.y);
                }
            }
            float sv[12];
#pragma unroll
            for (int j = 0; j < 12; j++) {
                float lo, hi; UPK(acc[j], lo, hi);
                sv[j] = lo + hi;
            }
#pragma unroll
            for (int j = 0; j < 12; j++)
                sv[j] += __shfl_xor_sync(0xffffffffu, sv[j], 1);
            if (hs == 0) {
#pragma unroll
                for (int cl = 0; cl < NCOL; cl++) {
                    S.pp[par][w][cl][rA]      = sv[cl * 2 + 0];
                    S.pp[par][w][cl][rA + 16] = sv[cl * 2 + 1];
                }
            }
        }
        __syncthreads();   // join: pp complete, sidxsh visible, gsh[t&1] visible

        // ---- D: bmv issue early; reduce k-split partials; P-mix; gates ----
        if (tid < 192) {
            float bmv = 0.f;
            if (rec) {
                int sidx = S.sidxsh;
                bmv = __ldcg(&g_G[(size_t)sidx * (C3 * Bz) + (size_t)mycolg * Bz + lane]);
            }
            float s = S.gsh[par][mycl][lane];
#pragma unroll
            for (int ww = 0; ww < 8; ww++) s += S.pp[par][ww][mycl][lane];
            S.ac[mycl][lane] = s;
            __syncwarp();
            unsigned long long a1 = 0ull, a2 = 0ull;
            const longlong2* prow1 = (const longlong2*)&S.Psh[lane][0];
            const longlong2* prow2 = (const longlong2*)&S.Psh[lane][32];
            const longlong2* arow  = (const longlong2*)&S.ac[mycl][0];   // uniform/broadcast
#pragma unroll
            for (int q = 0; q < 8; q++) {
                longlong2 av = arow[q];
                longlong2 p1 = prow1[q];
                FFMA2(a1, p1.x, av.x); FFMA2(a1, p1.y, av.y);
                longlong2 p2 = prow2[q];
                FFMA2(a2, p2.x, av.x); FFMA2(a2, p2.y, av.y);
            }
            float l1, h1, l2, h2;
            UPK(a1, l1, h1); UPK(a2, l2, h2);
            float y1 = l1 + h1, y2 = l2 + h2;
            g_G[(size_t)t * (C3 * Bz) + (size_t)mycolg * Bz + lane] = y2;  // Bm[t] (block-private)
            S.gt[mycl][lane] = S.biassh[mycl] + y1 + (rec ? bmv : y2);
        }
        __syncthreads();

        // ---- E: update+publish (warps 0-1) || prefetch G[t+1] (warps 6-7) ----
        if (tid < 64) {
            float gi = S.gt[w][lane], gf = S.gt[2 + w][lane], gg = S.gt[4 + w][lane];
            float iv = 1.f / (1.f + expf(-gi));
            float fv = 1.f / (1.f + expf(-gf));
            float gv = tanhf(gg);
            c_reg = fv * c_reg + iv * gv;
            float h = iv * tanhf(c_reg);   // o_t = i_t (faithful to source)
            g_pubh[par][lane * Hh + j0 + w] = h;
            if (t == T - 1) g_hfin[lane * Hh + j0 + w] = h;
            float v = S.Prsh[lane] * h * urj;
#pragma unroll
            for (int o = 16; o; o >>= 1) v += __shfl_xor_sync(0xffffffffu, v, o);
            if (lane == 0) S.s_gpp[w] = v;
            asm volatile("bar.sync 1, 64;");
            if (tid == 0) {
                float p = S.s_gpp[0] + S.s_gpp[1];
                asm volatile("st.release.gpu.global.v2.u32 [%0], {%1,%2};"
                             :: "l"(&g_syncp[par][bid]),
                                "r"((unsigned)(t + 1)), "r"(__float_as_uint(p))
                             : "memory");
            }
        } else if (tid >= 192 && tid < 240 && t + 1 < T) {
            int q = tid - 192;                 // 0..47
            int cl = q >> 3, qq = q & 7;
            int colg = (cl >> 1) * Hh + j0 + (cl & 1);
            const float* gp = &g_G[(size_t)(t + 1) * (C3 * Bz) + (size_t)colg * Bz + qq * 4];
            float4 v;
            v.x = __ldcg(gp); v.y = __ldcg(gp + 1);
            v.z = __ldcg(gp + 2); v.w = __ldcg(gp + 3);
            *(float4*)&S.gsh[(t + 1) & 1][cl][qq * 4] = v;
        }
        // no trailing barrier: per-step scratch is parity double-buffered;
        // remaining cross-step hazards are ordered by next step's C/D barriers.
    }

    // ---- final: out = h_final @ W_out + b_out (block 0) ----
    if (bid == 0) {
        if (tid < NB) {
            const uint2* ap = &g_syncp[(T - 1) & 1][tid];
            unsigned fl, pv;
            do {
                asm volatile("ld.acquire.gpu.global.v2.u32 {%0,%1}, [%2];"
                             : "=r"(fl), "=r"(pv) : "l"(ap) : "memory");
            } while (fl < (unsigned)T);
        }
        __syncthreads();
        int b = tid >> 3, ks = tid & 7;
        const float4* hr4 = (const float4*)(g_hfin + b * Hh);
        const float4* wo4 = (const float4*)W_out;
        float s = 0.f;
#pragma unroll
        for (int q = 0; q < 8; q++) {
            float4 hv = __ldcg(&hr4[ks * 8 + q]);
            float4 wv = wo4[ks * 8 + q];
            s += hv.x * wv.x + hv.y * wv.y + hv.z * wv.z + hv.w * wv.w;
        }
        s += __shfl_xor_sync(0xffffffffu, s, 1);
        s += __shfl_xor_sync(0xffffffffu, s, 2);
        s += __shfl_xor_sync(0xffffffffu, s, 4);
        if (ks == 0) out[b] = s + b_out[0];
    }
}

// ------------------------------------------------------------------
extern "C" void kernel_launch(void* const* d_in, const int* in_sizes, int n_in,
                              void* d_out, int out_size) {
    const float* x      = (const float*)d_in[0];   // [32,1024,256]
    const float* W      = (const float*)d_in[1];   // [256,1024]
    const float* U      = (const float*)d_in[2];   // [256,1024]
    const float* P      = (const float*)d_in[3];   // [32,64]
    const float* B_bias = (const float*)d_in[4];   // [1024]
    const float* W_r    = (const float*)d_in[5];   // [256,1]
    const float* P_r    = (const float*)d_in[6];   // [1,32]
    const float* U_r    = (const float*)d_in[7];   // [256,1]
    const float* W_out  = (const float*)d_in[8];   // [256,1]
    const float* b_out  = (const float*)d_in[9];   // [1]
    float* out = (float*)d_out;                    // [32,1]

    (void)in_sizes; (void)n_in; (void)out_size;

    init_kernel<<<1, NTH>>>();
    xr_kernel<<<T, 256>>>(x, W_r, P_r);
    gemm_kernel<<<dim3(12, T), 256>>>(x, W);

    cudaFuncSetAttribute(rec_kernel, cudaFuncAttributeMaxDynamicSharedMemorySize,
                         (int)sizeof(RecSmem));
    rec_kernel<<<NB, NTH, sizeof(RecSmem)>>>(U, P, B_bias, P_r, U_r, W_out, b_out, out);
}

// round 15
// speedup vs baseline: 1.3775x; 1.3775x over previous
#include <cuda_runtime.h>
#include <math.h>
#include <stddef.h>

// Problem constants
#define Bz    32
#define T     1024
#define F     256
#define Hh    256
#define C3    768      // 3 live gate chunks (i, f, g)
#define NB    64       // persistent blocks
#define HB    4        // H columns per block
#define NCOL  12       // HB * 3 chunks
#define NTH   256
#define OMEGA 32

// packed f32x2 helpers (Blackwell)
#define FFMA2(d, a, b) asm("fma.rn.f32x2 %0, %1, %2, %0;" : "+l"(d) : "l"(a), "l"(b))
#define UPK(v, lo, hi) asm("mov.b64 {%0, %1}, %2;" : "=f"(lo), "=f"(hi) : "l"(v))

// -------- device scratch (static; no cudaMalloc) --------
__device__ float        g_G[(size_t)T * C3 * Bz];  // [t][col][b]: x@W' -> overwritten with Bm[t]=P2@a_cur_t (block-private cols)
__device__ float        g_xrs[T];                  // sum_b P_r[b] * (x_t @ W_r)[b]
__device__ float        g_pubrec[2][NB][HB * Bz];  // packed h records: [slot][block][jl*32+b], 512B contiguous
__device__ float        g_gpay[T + 1];             // per-step accumulated gate partials (red.add.f32)
__device__ unsigned int g_cnt;                     // single monotonic step counter (red.add.u32)
__device__ float        g_hfin[Bz * Hh];           // final h for output

// ------------------------------------------------------------------
__global__ void init_kernel() {
    int tid = threadIdx.x;
    float* pr = (float*)g_pubrec;
    for (int i = tid; i < 2 * NB * HB * Bz; i += NTH) pr[i] = 0.f;
    for (int i = tid; i < T + 1; i += NTH) g_gpay[i] = 0.f;
    if (tid == 0) g_cnt = 0u;
}

// g_xrs[t] = sum_b P_r[b] * sum_f x[b,t,f] * W_r[f]
__global__ __launch_bounds__(256) void xr_kernel(const float* __restrict__ x,
                                                 const float* __restrict__ W_r,
                                                 const float* __restrict__ P_r) {
    __shared__ float xs[32];
    int t = blockIdx.x;
    int tid = threadIdx.x;
    int b = tid >> 3, ks = tid & 7;
    const float4* xv = (const float4*)(x + ((size_t)b * T + t) * F);
    const float4* wr = (const float4*)W_r;
    float s = 0.f;
#pragma unroll
    for (int q = 0; q < 8; q++) {
        float4 a = xv[ks * 8 + q];
        float4 w = wr[ks * 8 + q];
        s += a.x * w.x + a.y * w.y + a.z * w.z + a.w * w.w;
    }
    s += __shfl_xor_sync(0xffffffffu, s, 1);
    s += __shfl_xor_sync(0xffffffffu, s, 2);
    s += __shfl_xor_sync(0xffffffffu, s, 4);
    if (ks == 0) xs[b] = s * P_r[b];
    __syncthreads();
    if (tid < 32) {
        float v = xs[tid];
#pragma unroll
        for (int o = 16; o; o >>= 1) v += __shfl_xor_sync(0xffffffffu, v, o);
        if (tid == 0) g_xrs[t] = v;
    }
}

// G[t][col][b] = sum_f x[b,t,f] * W[f,col], col < 768. Grid: (12 col-tiles, 1024 t).
__global__ __launch_bounds__(256) void gemm_kernel(const float* __restrict__ x,
                                                   const float* __restrict__ W) {
    __shared__ float xsh[Bz][33];
    __shared__ float wsh[32][64];
    int t = blockIdx.y;
    int colbase = blockIdx.x * 64;
    int tid = threadIdx.x;
    int b = tid & 31, cg = tid >> 5;
    unsigned long long acc[4] = {0ull, 0ull, 0ull, 0ull};

    for (int kt = 0; kt < 8; kt++) {
        int k0 = kt * 32;
        __syncthreads();
        {
            int lb = tid >> 3, kq = tid & 7;
            float4 v = *(const float4*)(x + ((size_t)lb * T + t) * F + k0 + kq * 4);
            xsh[lb][kq * 4 + 0] = v.x; xsh[lb][kq * 4 + 1] = v.y;
            xsh[lb][kq * 4 + 2] = v.z; xsh[lb][kq * 4 + 3] = v.w;
            int kk = tid >> 3, c4 = (tid & 7) * 8;
            const float* wrow = W + (size_t)(k0 + kk) * 1024 + colbase + c4;
            *(float4*)&wsh[kk][c4] = *(const float4*)(wrow);
            *(float4*)&wsh[kk][c4 + 4] = *(const float4*)(wrow + 4);
        }
        __syncthreads();
#pragma unroll
        for (int kk = 0; kk < 32; kk++) {
            unsigned xu = __float_as_uint(xsh[b][kk]);
            unsigned long long xx;
            asm("mov.b64 %0, {%1, %1};" : "=l"(xx) : "r"(xu));
            const longlong2* wp = (const longlong2*)&wsh[kk][cg * 8];
            longlong2 w0 = wp[0], w1 = wp[1];
            FFMA2(acc[0], xx, w0.x); FFMA2(acc[1], xx, w0.y);
            FFMA2(acc[2], xx, w1.x); FFMA2(acc[3], xx, w1.y);
        }
    }
    size_t base = (size_t)t * (C3 * Bz) + (size_t)(colbase + cg * 8) * Bz + b;
#pragma unroll
    for (int i = 0; i < 4; i++) {
        float lo, hi; UPK(acc[i], lo, hi);
        g_G[base + (size_t)(2 * i) * Bz] = lo;
        g_G[base + (size_t)(2 * i + 1) * Bz] = hi;
    }
}

// ------------------------------------------------------------------
struct __align__(16) RecSmem {
    float hs[Bz][260];        // h transposed: hs[b][k], conflict-free
    float Ush[NCOL][260];     // 12 U' columns, k-contiguous (static)
    float Psh[Bz][68];        // P [32][64] padded (static)
    float pp[8][NCOL][Bz];    // per-warp k-split partials
    float gsh[2][NCOL][Bz];   // G[t] slice (x@W'), double-buffered
    float ac[NCOL][Bz];       // a_cur slice
    float gt[NCOL][Bz];       // gates slice
    float s_gpp[4];
    float Prsh[Bz];
    float biassh[NCOL];
    int   sidxsh;
};

__global__ __launch_bounds__(NTH, 1) void rec_kernel(
    const float* __restrict__ U, const float* __restrict__ P,
    const float* __restrict__ B_bias, const float* __restrict__ P_r,
    const float* __restrict__ U_r, const float* __restrict__ W_out,
    const float* __restrict__ b_out, float* __restrict__ out)
{
    extern __shared__ char smem_raw[];
    RecSmem& S = *reinterpret_cast<RecSmem*>(smem_raw);
    const int tid = threadIdx.x;
    const int w = tid >> 5, lane = tid & 31;
    const int bid = blockIdx.x;
    const int j0 = bid * HB;

    // ---- one-time preloads ----
    for (int i = tid; i < NCOL * Hh; i += NTH) {
        int cl = i >> 8, k = i & 255;
        int colg = (cl >> 2) * Hh + j0 + (cl & 3);
        S.Ush[cl][k] = U[(size_t)k * 1024 + colg];
    }
    for (int i = tid; i < Bz * 64; i += NTH) S.Psh[i >> 6][i & 63] = P[i];
    if (tid < Bz) S.Prsh[tid] = P_r[tid];
    if (tid < NCOL) {
        int colg = (tid >> 2) * Hh + j0 + (tid & 3);
        S.biassh[tid] = B_bias[colg];
    }
    if (tid < 96) {   // gsh[0] preload for t=0
        int cl = tid >> 3, qq = tid & 7;
        int colg = (cl >> 2) * Hh + j0 + (cl & 3);
        *(float4*)&S.gsh[0][cl][qq * 4] =
            *(const float4*)&g_G[(size_t)colg * Bz + qq * 4];
    }
    // D-phase constants (tid < 192): two columns per thread
    const int c0 = tid >> 5;                 // 0..5
    const int c1 = c0 + 6;
    const int colg0 = (c0 >> 2) * Hh + j0 + (c0 & 3);
    const int colg1 = (c1 >> 2) * Hh + j0 + (c1 & 3);
    // E-phase constants (tid < 128): jl = w (0..3), b = lane
    float urj = (tid < 128) ? U_r[j0 + w] : 0.f;
    float c_reg = 0.f;                       // c state for (jl=w, b=lane), tid<128
    // C-phase gather constants: thread owns k = tid
    const int grec = tid >> 2, gjj = tid & 3;
    __syncthreads();

    for (int t = 0; t < T; t++) {
        const int slot = (t - 1) & 1;   // records published at step t-1 (t=0: zeros)
        const int par  = t & 1;
        const bool rec = (t >= OMEGA);

        // ---- A: single spinner (tid0) on the one counter; gate + idx ----
        if (tid == 0) {
            if (t > 0) {
                unsigned v;
                do {
                    asm volatile("ld.acquire.gpu.global.u32 %0, [%1];"
                                 : "=r"(v) : "l"(&g_cnt) : "memory");
                } while (v < (unsigned)(NB * t));
            }
            if (rec) {
                float g = __ldcg(&g_gpay[t]) + g_xrs[t];
                float gate = 1.f / (1.f + expf(-g));
                int hi = t - 1;
                int idx = (int)rintf((float)t * gate);
                idx = idx < 0 ? 0 : (idx > hi ? hi : idx);
                S.sidxsh = idx;
            }
        }
        __syncthreads();

        // ---- C1: gather h from 64 packed records -> hs[b][k] (thread owns k=tid) ----
        {
            const float4* src = (const float4*)&g_pubrec[slot][grec][gjj * Bz];
            float4 hv[8];
#pragma unroll
            for (int i = 0; i < 8; i++) hv[i] = __ldcg(&src[i]);
#pragma unroll
            for (int i = 0; i < 8; i++) {
                S.hs[4 * i + 0][tid] = hv[i].x;
                S.hs[4 * i + 1][tid] = hv[i].y;
                S.hs[4 * i + 2][tid] = hv[i].z;
                S.hs[4 * i + 3][tid] = hv[i].w;
            }
        }
        __syncthreads();

        // ---- C2: matvec h@U' (f32x2, k-split over 8 warps, 12 cols) ----
        {
            unsigned long long acc[NCOL];
#pragma unroll
            for (int cl = 0; cl < NCOL; cl++) acc[cl] = 0ull;
            const longlong2* hrow = (const longlong2*)&S.hs[lane][0];
#pragma unroll
            for (int q = 0; q < 8; q++) {
                longlong2 hq = hrow[w * 8 + q];
#pragma unroll
                for (int cl = 0; cl < NCOL; cl++) {
                    longlong2 uq = ((const longlong2*)&S.Ush[cl][0])[w * 8 + q];  // broadcast
                    FFMA2(acc[cl], hq.x, uq.x);
                    FFMA2(acc[cl], hq.y, uq.y);
                }
            }
#pragma unroll
            for (int cl = 0; cl < NCOL; cl++) {
                float lo, hi; UPK(acc[cl], lo, hi);
                S.pp[w][cl][lane] = lo + hi;
            }
        }
        __syncthreads();

        // ---- D: bmv early; reduce k-split partials; P-mix; gates (2 cols/thread) ----
        if (tid < 192) {
            float bmv0 = 0.f, bmv1 = 0.f;
            if (rec) {
                int sidx = S.sidxsh;
                const float* gb = &g_G[(size_t)sidx * (C3 * Bz)];
                bmv0 = __ldcg(&gb[(size_t)colg0 * Bz + lane]);
                bmv1 = __ldcg(&gb[(size_t)colg1 * Bz + lane]);
            }
            float s0 = S.gsh[par][c0][lane];
            float s1 = S.gsh[par][c1][lane];
#pragma unroll
            for (int ww = 0; ww < 8; ww++) {
                s0 += S.pp[ww][c0][lane];
                s1 += S.pp[ww][c1][lane];
            }
            S.ac[c0][lane] = s0;
            S.ac[c1][lane] = s1;
            __syncwarp();
            unsigned long long a10 = 0ull, a20 = 0ull, a11 = 0ull, a21 = 0ull;
            const longlong2* prow1 = (const longlong2*)&S.Psh[lane][0];
            const longlong2* prow2 = (const longlong2*)&S.Psh[lane][32];
            const longlong2* ar0   = (const longlong2*)&S.ac[c0][0];   // broadcast
            const longlong2* ar1   = (const longlong2*)&S.ac[c1][0];
#pragma unroll
            for (int q = 0; q < 8; q++) {
                longlong2 p1 = prow1[q], p2 = prow2[q];
                longlong2 v0 = ar0[q], v1 = ar1[q];
                FFMA2(a10, p1.x, v0.x); FFMA2(a10, p1.y, v0.y);
                FFMA2(a20, p2.x, v0.x); FFMA2(a20, p2.y, v0.y);
                FFMA2(a11, p1.x, v1.x); FFMA2(a11, p1.y, v1.y);
                FFMA2(a21, p2.x, v1.x); FFMA2(a21, p2.y, v1.y);
            }
            float l, h, y10, y20, y11, y21;
            UPK(a10, l, h); y10 = l + h;
            UPK(a20, l, h); y20 = l + h;
            UPK(a11, l, h); y11 = l + h;
            UPK(a21, l, h); y21 = l + h;
            float* gt0 = &g_G[(size_t)t * (C3 * Bz)];
            gt0[(size_t)colg0 * Bz + lane] = y20;   // Bm[t] (block-private cols)
            gt0[(size_t)colg1 * Bz + lane] = y21;
            S.gt[c0][lane] = S.biassh[c0] + y10 + (rec ? bmv0 : y20);
            S.gt[c1][lane] = S.biassh[c1] + y11 + (rec ? bmv1 : y21);
        }
        __syncthreads();

        // ---- E: update + packed publish (tid<128) || prefetch G[t+1] (tid 128-223) ----
        if (tid < 128) {
            float gi = S.gt[w][lane], gf = S.gt[4 + w][lane], gg = S.gt[8 + w][lane];
            float iv = 1.f / (1.f + expf(-gi));
            float fv = 1.f / (1.f + expf(-gf));
            float gv = tanhf(gg);
            c_reg = fv * c_reg + iv * gv;
            float h = iv * tanhf(c_reg);   // o_t = i_t (faithful to source)
            g_pubrec[par][bid][w * Bz + lane] = h;   // contiguous 512B per block
            if (t == T - 1) g_hfin[lane * Hh + j0 + w] = h;
            float v = S.Prsh[lane] * h * urj;
#pragma unroll
            for (int o = 16; o; o >>= 1) v += __shfl_xor_sync(0xffffffffu, v, o);
            if (lane == 0) S.s_gpp[w] = v;
            asm volatile("bar.sync 1, 128;");
            if (tid == 0) {
                float p = (S.s_gpp[0] + S.s_gpp[1]) + (S.s_gpp[2] + S.s_gpp[3]);
                // release ordering: h stores + gpay add drain before cnt bump is visible
                asm volatile("red.release.gpu.global.add.f32 [%0], %1;"
                             :: "l"(&g_gpay[t + 1]), "f"(p) : "memory");
                asm volatile("red.release.gpu.global.add.u32 [%0], %1;"
                             :: "l"(&g_cnt), "r"(1u) : "memory");
            }
        } else if (tid < 224 && t + 1 < T) {
            int q = tid - 128;                 // 0..95
            int cl = q >> 3, qq = q & 7;
            int colg = (cl >> 2) * Hh + j0 + (cl & 3);
            const float* gp = &g_G[(size_t)(t + 1) * (C3 * Bz) + (size_t)colg * Bz + qq * 4];
            float4 v;
            v.x = __ldcg(gp); v.y = __ldcg(gp + 1);
            v.z = __ldcg(gp + 2); v.w = __ldcg(gp + 3);
            *(float4*)&S.gsh[(t + 1) & 1][cl][qq * 4] = v;
        }
        // no trailing barrier: next step's A-barrier orders smem reuse
    }

    // ---- final: out = h_final @ W_out + b_out (block 0) ----
    if (bid == 0) {
        if (tid == 0) {
            unsigned v;
            do {
                asm volatile("ld.acquire.gpu.global.u32 %0, [%1];"
                             : "=r"(v) : "l"(&g_cnt) : "memory");
            } while (v < (unsigned)(NB * T));
        }
        __syncthreads();
        int b = tid >> 3, ks = tid & 7;
        const float4* hr4 = (const float4*)(g_hfin + b * Hh);
        const float4* wo4 = (const float4*)W_out;
        float s = 0.f;
#pragma unroll
        for (int q = 0; q < 8; q++) {
            float4 hv = __ldcg(&hr4[ks * 8 + q]);
            float4 wv = wo4[ks * 8 + q];
            s += hv.x * wv.x + hv.y * wv.y + hv.z * wv.z + hv.w * wv.w;
        }
        s += __shfl_xor_sync(0xffffffffu, s, 1);
        s += __shfl_xor_sync(0xffffffffu, s, 2);
        s += __shfl_xor_sync(0xffffffffu, s, 4);
        if (ks == 0) out[b] = s + b_out[0];
    }
}

// ------------------------------------------------------------------
extern "C" void kernel_launch(void* const* d_in, const int* in_sizes, int n_in,
                              void* d_out, int out_size) {
    const float* x      = (const float*)d_in[0];   // [32,1024,256]
    const float* W      = (const float*)d_in[1];   // [256,1024]
    const float* U      = (const float*)d_in[2];   // [256,1024]
    const float* P      = (const float*)d_in[3];   // [32,64]
    const float* B_bias = (const float*)d_in[4];   // [1024]
    const float* W_r    = (const float*)d_in[5];   // [256,1]
    const float* P_r    = (const float*)d_in[6];   // [1,32]
    const float* U_r    = (const float*)d_in[7];   // [256,1]
    const float* W_out  = (const float*)d_in[8];   // [256,1]
    const float* b_out  = (const float*)d_in[9];   // [1]
    float* out = (float*)d_out;                    // [32,1]

    (void)in_sizes; (void)n_in; (void)out_size;

    init_kernel<<<1, NTH>>>();
    xr_kernel<<<T, 256>>>(x, W_r, P_r);
    gemm_kernel<<<dim3(12, T), 256>>>(x, W);

    cudaFuncSetAttribute(rec_kernel, cudaFuncAttributeMaxDynamicSharedMemorySize,
                         (int)sizeof(RecSmem));
    rec_kernel<<<NB, NTH, sizeof(RecSmem)>>>(U, P, B_bias, P_r, U_r, W_out, b_out, out);
}